// round 10
// baseline (speedup 1.0000x reference)
#include <cuda_runtime.h>
#include <cstdint>

// Problem constants (fixed: midis_out is (16, 11, 65536) fp32, LST=64)
#define NB      16
#define NI      11
#define NT      65536
#define LSTLEN  64
#define CHUNK   1024
#define NTB     (CHUNK / LSTLEN)    // 16 time-blocks per CTA
#define THREADS 256
#define NWARP   (THREADS / 32)
#define NCHUNK  (NT / CHUNK)        // 64
#define NTASK   (NI * NTB)          // 176 time-block tasks
#define NGRP    (NTASK / 4)         // 44 groups of 4 tasks
#define ROW_BYTES  (CHUNK * 4)      // 4096 B per tile row
#define TILE_BYTES (NI * ROW_BYTES) // 45056 B

__device__ __forceinline__ void ce(float& a, float& b) {
    const float lo = fminf(a, b), hi = fmaxf(a, b);
    a = lo; b = hi;
}

// Optimal 11-input sorting network (35 CE, depth 8), ascending.
__device__ __forceinline__ void sort11(float z[NI]) {
    ce(z[0],z[9]); ce(z[1],z[6]); ce(z[2],z[4]); ce(z[3],z[7]); ce(z[5],z[8]);
    ce(z[0],z[1]); ce(z[3],z[5]); ce(z[4],z[10]); ce(z[6],z[9]); ce(z[7],z[8]);
    ce(z[1],z[3]); ce(z[2],z[5]); ce(z[4],z[7]); ce(z[8],z[10]);
    ce(z[0],z[4]); ce(z[1],z[2]); ce(z[3],z[7]); ce(z[5],z[9]); ce(z[6],z[8]);
    ce(z[0],z[1]); ce(z[2],z[6]); ce(z[4],z[5]); ce(z[7],z[8]); ce(z[9],z[10]);
    ce(z[2],z[4]); ce(z[3],z[6]); ce(z[5],z[7]); ce(z[8],z[9]);
    ce(z[1],z[2]); ce(z[3],z[4]); ce(z[5],z[6]); ce(z[7],z[8]);
    ce(z[2],z[3]); ce(z[4],z[5]); ce(z[6],z[7]);
}

// Exact sparsemax tau over 11 values (destroys z).
// tau* = max_{k=1..d} (csum_k - 1)/k over the DESCENDING cumsum.
__device__ __forceinline__ float sparsemax11_tau(float z[NI]) {
    sort11(z);
    float cs  = z[NI - 1];
    float tau = cs - 1.0f;
    #pragma unroll
    for (int k = 2; k <= NI; ++k) {
        cs += z[NI - k];
        const float rk = 1.0f / (float)k;          // compile-time constant
        tau = fmaxf(tau, fmaf(cs, rk, -rk));       // (cs-1)/k
    }
    return tau;
}

__device__ __forceinline__ void mbar_wait_parity0(uint32_t mbar_addr) {
    uint32_t done;
    asm volatile(
        "{\n\t.reg .pred p;\n\t"
        "mbarrier.try_wait.parity.acquire.cta.shared::cta.b64 p, [%1], 0;\n\t"
        "selp.b32 %0, 1, 0, p;\n\t}"
        : "=r"(done) : "r"(mbar_addr) : "memory");
    if (!done) {
        asm volatile(
            "{\n\t.reg .pred P1;\n\t"
            "WAIT_LOOP_%=:\n\t"
            "mbarrier.try_wait.parity.acquire.cta.shared::cta.b64 P1, [%0], 0, 0x989680;\n\t"
            "@P1 bra.uni WAIT_DONE_%=;\n\t"
            "bra.uni WAIT_LOOP_%=;\n\t"
            "WAIT_DONE_%=:\n\t}"
            :: "r"(mbar_addr) : "memory");
    }
}

__global__ __launch_bounds__(THREADS, 5)
void multiply_sparsemax_kernel(const float* __restrict__ in,
                               float* __restrict__ out)
{
    __shared__ __align__(16) float xs[NI * CHUNK];  // 45056 B tile
    __shared__ float tau_time[NTASK];               // tau per (inst, 64-block)
    __shared__ __align__(8) unsigned long long mbar;

    const int tid  = threadIdx.x;
    const int wid  = tid >> 5;
    const int lane = tid & 31;

    const int b = blockIdx.x / NCHUNK;
    const int c = blockIdx.x % NCHUNK;
    const unsigned base = (unsigned)(b * NI) * NT + (unsigned)(c * CHUNK);

    // ---- Load tile via bulk-async copy: 11 rows x 4096 B ----
    const uint32_t mbar_addr = (uint32_t)__cvta_generic_to_shared(&mbar);
    const uint32_t xs_addr   = (uint32_t)__cvta_generic_to_shared(xs);
    if (tid == 0)
        asm volatile("mbarrier.init.shared.b64 [%0], 1;" :: "r"(mbar_addr) : "memory");
    __syncthreads();
    if (tid == 0) {
        asm volatile("mbarrier.arrive.expect_tx.shared.b64 _, [%0], %1;"
                     :: "r"(mbar_addr), "r"((uint32_t)TILE_BYTES) : "memory");
        const float* src = in + base;
        #pragma unroll
        for (int i = 0; i < NI; ++i) {
            asm volatile(
                "cp.async.bulk.shared::cluster.global.mbarrier::complete_tx::bytes "
                "[%0], [%1], %2, [%3];"
                :: "r"(xs_addr + (uint32_t)(i * ROW_BYTES)),
                   "l"(src + (size_t)i * NT),
                   "r"((uint32_t)ROW_BYTES),
                   "r"(mbar_addr) : "memory");
        }
    }
    mbar_wait_parity0(mbar_addr);   // tile resident (acquire orders LDS after)

    // ---- Phase A: tau over 64-length time blocks ----
    // 4 tasks/warp (8-lane segments, 8 elems/lane). Michelot from the safe
    // warm start tau0 = max-1; 2 unconditional iterations + convergence-
    // checked guard loop (the check IS a full Michelot pass -> exact).
    {
        const int seg = lane >> 3;
        const int sl  = lane & 7;
        for (int g = wid; g < NGRP; g += NWARP) {
            const int task = g * 4 + seg;
            const float* p = xs + (task >> 4) * CHUNK + (task & 15) * LSTLEN + sl * 8;
            const float4 v0 = *(const float4*)p;
            const float4 v1 = *(const float4*)(p + 4);
            const float z0 = v0.x, z1 = v0.y, z2 = v0.z, z3 = v0.w;
            const float z4 = v1.x, z5 = v1.y, z6 = v1.z, z7 = v1.w;

            float m = fmaxf(fmaxf(fmaxf(z0, z1), fmaxf(z2, z3)),
                            fmaxf(fmaxf(z4, z5), fmaxf(z6, z7)));
            #pragma unroll
            for (int o = 4; o; o >>= 1)
                m = fmaxf(m, __shfl_xor_sync(0xFFFFFFFFu, m, o));

            float tau = m - 1.0f;
            float cf  = 0.0f;

            #pragma unroll
            for (int it = 0; it < 2; ++it) {
                float ss = 0.0f; cf = 0.0f;
                if (z0 > tau) { ss += z0; cf += 1.0f; }
                if (z1 > tau) { ss += z1; cf += 1.0f; }
                if (z2 > tau) { ss += z2; cf += 1.0f; }
                if (z3 > tau) { ss += z3; cf += 1.0f; }
                if (z4 > tau) { ss += z4; cf += 1.0f; }
                if (z5 > tau) { ss += z5; cf += 1.0f; }
                if (z6 > tau) { ss += z6; cf += 1.0f; }
                if (z7 > tau) { ss += z7; cf += 1.0f; }
                #pragma unroll
                for (int o = 4; o; o >>= 1) {
                    ss += __shfl_xor_sync(0xFFFFFFFFu, ss, o);
                    cf += __shfl_xor_sync(0xFFFFFFFFu, cf, o);
                }
                tau = __fdividef(ss - 1.0f, cf);
            }

            int k = (int)cf;
            #pragma unroll 1
            for (;;) {
                float ss = 0.0f, c2 = 0.0f;
                if (z0 > tau) { ss += z0; c2 += 1.0f; }
                if (z1 > tau) { ss += z1; c2 += 1.0f; }
                if (z2 > tau) { ss += z2; c2 += 1.0f; }
                if (z3 > tau) { ss += z3; c2 += 1.0f; }
                if (z4 > tau) { ss += z4; c2 += 1.0f; }
                if (z5 > tau) { ss += z5; c2 += 1.0f; }
                if (z6 > tau) { ss += z6; c2 += 1.0f; }
                if (z7 > tau) { ss += z7; c2 += 1.0f; }
                #pragma unroll
                for (int o = 4; o; o >>= 1) {
                    ss += __shfl_xor_sync(0xFFFFFFFFu, ss, o);
                    c2 += __shfl_xor_sync(0xFFFFFFFFu, c2, o);
                }
                const int kn = (int)c2;
                const bool conv = (kn >= k);
                if (__all_sync(0xFFFFFFFFu, conv)) break;
                if (!conv) { tau = __fdividef(ss - 1.0f, c2); k = kn; }
            }
            if (sl == 0) tau_time[task] = tau;
        }
    }

    // ---- Phase B: instrument sparsemax for 4 adjacent columns per thread
    //      (two sequential pairs to bound register pressure). Depends only
    //      on xs -> runs BEFORE the barrier to hide Phase-A skew. ----
    const int t0 = tid * 4;
    float ta0, ta1, ta2, ta3;
    {
        float za[NI], zb[NI];
        #pragma unroll
        for (int i = 0; i < NI; ++i) {
            const float2 v = *(const float2*)(xs + i * CHUNK + t0);
            za[i] = v.x; zb[i] = v.y;
        }
        ta0 = sparsemax11_tau(za);
        ta1 = sparsemax11_tau(zb);
        #pragma unroll
        for (int i = 0; i < NI; ++i) {
            const float2 v = *(const float2*)(xs + i * CHUNK + t0 + 2);
            za[i] = v.x; zb[i] = v.y;
        }
        ta2 = sparsemax11_tau(za);
        ta3 = sparsemax11_tau(zb);
    }

    __syncthreads();                         // tau_time now visible

    // ---- Phase C: fused epilogue, float4/STG.128, taus in registers ----
    {
        const int blkb = t0 >> 6;            // fixed per thread
        const float* px = xs + t0;
        float* po = out + base + (unsigned)t0;
        #pragma unroll
        for (int i = 0; i < NI; ++i) {
            const float  tt = tau_time[i * NTB + blkb];
            const float4 v  = *(const float4*)(px + i * CHUNK);
            float4 r;
            r.x = fmaxf(v.x - ta0, 0.0f) * fmaxf(v.x - tt, 0.0f);
            r.y = fmaxf(v.y - ta1, 0.0f) * fmaxf(v.y - tt, 0.0f);
            r.z = fmaxf(v.z - ta2, 0.0f) * fmaxf(v.z - tt, 0.0f);
            r.w = fmaxf(v.w - ta3, 0.0f) * fmaxf(v.w - tt, 0.0f);
            *(float4*)(po + (unsigned)(i * NT)) = r;
        }
    }
}

extern "C" void kernel_launch(void* const* d_in, const int* in_sizes, int n_in,
                              void* d_out, int out_size)
{
    const float* in = (const float*)d_in[0];
    float* out = (float*)d_out;
    multiply_sparsemax_kernel<<<NB * NCHUNK, THREADS>>>(in, out);
}

// round 11
// speedup vs baseline: 1.0647x; 1.0647x over previous
#include <cuda_runtime.h>
#include <cstdint>

// Problem constants (fixed: midis_out is (16, 11, 65536) fp32, LST=64)
#define NB      16
#define NI      11
#define NT      65536
#define LSTLEN  64
#define NBLK    (NB * NI * (NT / LSTLEN))   // 180224 time-blocks total
#define CHUNK   512                          // columns per CTA in kernel 2
#define THREADS 256
#define NCHUNK  (NT / CHUNK)                 // 128

// Scratch for per-64-block taus (allocation-free: device global)
__device__ float g_tau_time[NBLK];

// ============================ Kernel 1 =====================================
// tau for every 64-length time block. Block g = 64 contiguous floats at
// in[g*64]. One warp processes 4 blocks via 8-lane segments (8 elems/lane).
// Michelot fixed point from the safe warm start tau0 = max-1 (tau* >= max-1
// always since the max output <= 1): 2 unconditional iterations, then a
// convergence-checked guard loop (the check IS a full pass -> exact).
__global__ __launch_bounds__(THREADS)
void tau_time_kernel(const float* __restrict__ in)
{
    const int lane = threadIdx.x & 31;
    const int gwarp = (blockIdx.x * (THREADS / 32)) + (threadIdx.x >> 5);
    const int seg = lane >> 3;            // which of 4 blocks
    const int sl  = lane & 7;             // sub-lane within block

    const int blk = gwarp * 4 + seg;      // NBLK is divisible by 4
    const float* p = in + (size_t)blk * LSTLEN + sl * 8;
    const float4 v0 = *(const float4*)p;
    const float4 v1 = *(const float4*)(p + 4);
    const float z0 = v0.x, z1 = v0.y, z2 = v0.z, z3 = v0.w;
    const float z4 = v1.x, z5 = v1.y, z6 = v1.z, z7 = v1.w;

    float m = fmaxf(fmaxf(fmaxf(z0, z1), fmaxf(z2, z3)),
                    fmaxf(fmaxf(z4, z5), fmaxf(z6, z7)));
    #pragma unroll
    for (int o = 4; o; o >>= 1)
        m = fmaxf(m, __shfl_xor_sync(0xFFFFFFFFu, m, o));

    float tau = m - 1.0f;
    float cf  = 0.0f;

    #pragma unroll
    for (int it = 0; it < 2; ++it) {
        float ss = 0.0f; cf = 0.0f;
        if (z0 > tau) { ss += z0; cf += 1.0f; }
        if (z1 > tau) { ss += z1; cf += 1.0f; }
        if (z2 > tau) { ss += z2; cf += 1.0f; }
        if (z3 > tau) { ss += z3; cf += 1.0f; }
        if (z4 > tau) { ss += z4; cf += 1.0f; }
        if (z5 > tau) { ss += z5; cf += 1.0f; }
        if (z6 > tau) { ss += z6; cf += 1.0f; }
        if (z7 > tau) { ss += z7; cf += 1.0f; }
        #pragma unroll
        for (int o = 4; o; o >>= 1) {
            ss += __shfl_xor_sync(0xFFFFFFFFu, ss, o);
            cf += __shfl_xor_sync(0xFFFFFFFFu, cf, o);
        }
        tau = __fdividef(ss - 1.0f, cf);
    }

    int k = (int)cf;
    #pragma unroll 1
    for (;;) {
        float ss = 0.0f, c2 = 0.0f;
        if (z0 > tau) { ss += z0; c2 += 1.0f; }
        if (z1 > tau) { ss += z1; c2 += 1.0f; }
        if (z2 > tau) { ss += z2; c2 += 1.0f; }
        if (z3 > tau) { ss += z3; c2 += 1.0f; }
        if (z4 > tau) { ss += z4; c2 += 1.0f; }
        if (z5 > tau) { ss += z5; c2 += 1.0f; }
        if (z6 > tau) { ss += z6; c2 += 1.0f; }
        if (z7 > tau) { ss += z7; c2 += 1.0f; }
        #pragma unroll
        for (int o = 4; o; o >>= 1) {
            ss += __shfl_xor_sync(0xFFFFFFFFu, ss, o);
            c2 += __shfl_xor_sync(0xFFFFFFFFu, c2, o);
        }
        const int kn = (int)c2;
        const bool conv = (kn >= k);
        if (__all_sync(0xFFFFFFFFu, conv)) break;
        if (!conv) { tau = __fdividef(ss - 1.0f, c2); k = kn; }
    }
    if (sl == 0) g_tau_time[blk] = tau;
}

// ============================ Kernel 2 =====================================

__device__ __forceinline__ void ce(float& a, float& b) {
    const float lo = fminf(a, b), hi = fmaxf(a, b);
    a = lo; b = hi;
}

// Optimal 11-input sorting network (35 CE, depth 8), ascending.
__device__ __forceinline__ void sort11(float z[NI]) {
    ce(z[0],z[9]); ce(z[1],z[6]); ce(z[2],z[4]); ce(z[3],z[7]); ce(z[5],z[8]);
    ce(z[0],z[1]); ce(z[3],z[5]); ce(z[4],z[10]); ce(z[6],z[9]); ce(z[7],z[8]);
    ce(z[1],z[3]); ce(z[2],z[5]); ce(z[4],z[7]); ce(z[8],z[10]);
    ce(z[0],z[4]); ce(z[1],z[2]); ce(z[3],z[7]); ce(z[5],z[9]); ce(z[6],z[8]);
    ce(z[0],z[1]); ce(z[2],z[6]); ce(z[4],z[5]); ce(z[7],z[8]); ce(z[9],z[10]);
    ce(z[2],z[4]); ce(z[3],z[6]); ce(z[5],z[7]); ce(z[8],z[9]);
    ce(z[1],z[2]); ce(z[3],z[4]); ce(z[5],z[6]); ce(z[7],z[8]);
    ce(z[2],z[3]); ce(z[4],z[5]); ce(z[6],z[7]);
}

// Exact sparsemax tau over 11 values (destroys z).
// tau* = max_{k=1..d} (csum_k - 1)/k over the DESCENDING cumsum.
__device__ __forceinline__ float sparsemax11_tau(float z[NI]) {
    sort11(z);
    float cs  = z[NI - 1];
    float tau = cs - 1.0f;
    #pragma unroll
    for (int k = 2; k <= NI; ++k) {
        cs += z[NI - k];
        const float rk = 1.0f / (float)k;          // compile-time constant
        tau = fmaxf(tau, fmaf(cs, rk, -rk));       // (cs-1)/k
    }
    return tau;
}

// Per-column instrument sparsemax + multiply, no SMEM, no barriers.
// Thread -> 2 adjacent columns; warp -> 64 columns = exactly one 64-block,
// so the tau_time addresses are warp-uniform (broadcast loads, L1-hot).
__global__ __launch_bounds__(THREADS)
void sparsemax_mul_kernel(const float* __restrict__ in,
                          float* __restrict__ out)
{
    const int tid = threadIdx.x;
    const int b = blockIdx.x / NCHUNK;
    const int c = blockIdx.x % NCHUNK;
    const int t0 = tid * 2;
    const unsigned base = (unsigned)(b * NI) * NT + (unsigned)(c * CHUNK) + (unsigned)t0;

    float2 v[NI];
    float za[NI], zb[NI];
    #pragma unroll
    for (int i = 0; i < NI; ++i) {
        v[i] = *(const float2*)(in + base + (unsigned)(i * NT));
        za[i] = v[i].x; zb[i] = v[i].y;
    }
    const float ta = sparsemax11_tau(za);
    const float tb = sparsemax11_tau(zb);

    // warp-uniform 64-block index within this (b, chunk)
    const int blkb = (b * NI) * (NT / LSTLEN) + c * (CHUNK / LSTLEN) + (t0 >> 6);
    #pragma unroll
    for (int i = 0; i < NI; ++i) {
        const float tt = g_tau_time[blkb + i * (NT / LSTLEN)];
        float2 r;
        r.x = fmaxf(v[i].x - ta, 0.0f) * fmaxf(v[i].x - tt, 0.0f);
        r.y = fmaxf(v[i].y - tb, 0.0f) * fmaxf(v[i].y - tt, 0.0f);
        *(float2*)(out + base + (unsigned)(i * NT)) = r;
    }
}

extern "C" void kernel_launch(void* const* d_in, const int* in_sizes, int n_in,
                              void* d_out, int out_size)
{
    const float* in = (const float*)d_in[0];
    float* out = (float*)d_out;
    // Kernel 1: 180224 blocks, 32 per CTA (8 warps x 4 segment-tasks)
    tau_time_kernel<<<NBLK / 32, THREADS>>>(in);
    // Kernel 2: 2048 CTAs x 256 threads, 2 columns per thread
    sparsemax_mul_kernel<<<NB * NCHUNK, THREADS>>>(in, out);
}